// round 11
// baseline (speedup 1.0000x reference)
#include <cuda_runtime.h>
#include <cuda_bf16.h>
#include <math.h>
#include <stdint.h>

// Problem constants
#define B_  2
#define T_  1024
#define S_  2048
#define D_  1024
#define H_  16
#define HD_ 64
#define SCALE_ 0.125f
#define RMS_EPS_ 1e-6f

#define NS_ 2
#define SPS (S_ / NS_)

// bf16-split GEMM config
#define KTOT (3 * D_)
#define KB2 64                    // bf16 K per stage
#define NITER2 (KTOT / KB2)       // 48
#define GTN 128
#define GPITCH 144                // smem row pitch bytes (64 bf16 + pad)
#define WSTAGE (128 * GPITCH)     // W stage bytes

// attention mma config
#define AM 128           // query rows per CTA (8 warps x 16)
#define AKE 192          // extended K dim (3 x 64)
#define APB 400          // smem row pitch bytes
#define ATTN_SMEM ((AM + 64 + 64) * APB)  // 102400

// Scratch (device globals; no allocation allowed)
__device__ float g_v[B_ * S_ * D_];
__device__ float g_proj[B_ * T_ * D_];
__device__ float g_pacc[NS_ * B_ * H_ * T_ * HD_];
__device__ float g_pm[NS_ * B_ * H_ * T_];
__device__ float g_pl[NS_ * B_ * H_ * T_];
// bf16 split operands (projection GEMMs)
__device__ __nv_bfloat16 g_qs[(size_t)B_ * T_ * KTOT];
__device__ __nv_bfloat16 g_cs[(size_t)B_ * S_ * KTOT];
__device__ __nv_bfloat16 g_as[(size_t)B_ * T_ * KTOT];
__device__ __nv_bfloat16 g_wqs[(size_t)D_ * KTOT];
__device__ __nv_bfloat16 g_wks[(size_t)D_ * KTOT];
__device__ __nv_bfloat16 g_wvs[(size_t)D_ * KTOT];
__device__ __nv_bfloat16 g_wos[(size_t)D_ * KTOT];
// attention extended operands
__device__ __nv_bfloat16 g_qe[(size_t)B_ * H_ * T_ * AKE];        // [qhi|qhi|qlo]
__device__ __nv_bfloat16 g_ke[(size_t)B_ * H_ * S_ * AKE];        // [khi|klo|khi]
__device__ __nv_bfloat16 g_vte[(size_t)B_ * H_ * HD_ * 2 * S_];   // V^T [d][vhi(S)|vlo(S)]

// ============================ PTX helpers (base ISA) ========================
__device__ __forceinline__ uint32_t smem_u32(const void* p) {
    uint32_t a;
    asm("{ .reg .u64 t; cvta.to.shared.u64 t, %1; cvt.u32.u64 %0, t; }"
        : "=r"(a) : "l"(p));
    return a;
}

#define CP_ASYNC16(dst_u32, src_ptr) \
    asm volatile("cp.async.cg.shared.global [%0], [%1], 16;" \
        :: "r"(dst_u32), "l"(src_ptr))
#define CP_COMMIT() asm volatile("cp.async.commit_group;" ::: "memory")
#define CP_WAIT1()  asm volatile("cp.async.wait_group 1;" ::: "memory")
#define CP_WAIT0()  asm volatile("cp.async.wait_group 0;" ::: "memory")

#define LDMATRIX_X4(r0, r1, r2, r3, addr) \
    asm volatile("ldmatrix.sync.aligned.m8n8.x4.shared.b16 {%0,%1,%2,%3}, [%4];" \
        : "=r"(r0), "=r"(r1), "=r"(r2), "=r"(r3) : "r"(addr))

#define MMA16816(d0, d1, d2, d3, a0, a1, a2, a3, b0, b1) \
    asm volatile("mma.sync.aligned.m16n8k16.row.col.f32.bf16.bf16.f32 " \
        "{%0,%1,%2,%3}, {%4,%5,%6,%7}, {%8,%9}, {%0,%1,%2,%3};" \
        : "+f"(d0), "+f"(d1), "+f"(d2), "+f"(d3) \
        : "r"(a0), "r"(a1), "r"(a2), "r"(a3), "r"(b0), "r"(b1))

__device__ __forceinline__ uint32_t pack_bf16x2(float p0, float p1) {
    uint32_t d;
    asm("cvt.rn.bf16x2.f32 %0, %1, %2;" : "=r"(d) : "f"(p1), "f"(p0));
    return d;
}
__device__ __forceinline__ float bf16lo_f(uint32_t u) {
    return __uint_as_float(u << 16);
}
__device__ __forceinline__ float bf16hi_f(uint32_t u) {
    return __uint_as_float(u & 0xffff0000u);
}

// ---------------------------------------------------------------------------
// Mega split kernel: all input conversions in one launch.
//  blocks [0, 2048)        : act split query row -> g_qs     [hi|hi|lo]
//  blocks [2048, 6144)     : act split context row -> g_cs   [hi|hi|lo]
//  blocks [6144, 10240)    : wgt split (Wq,Wk,Wv,Wo) -> g_w*s [hi|lo|hi]
// ---------------------------------------------------------------------------
__global__ __launch_bounds__(256) void split_all(
    const float* __restrict__ query, const float* __restrict__ context,
    const float* __restrict__ Wq, const float* __restrict__ Wk,
    const float* __restrict__ Wv, const float* __restrict__ Wo)
{
    const int bid = blockIdx.x;
    const float* in;
    __nv_bfloat16* out;
    int act;
    if (bid < 2048) {
        in = query + (size_t)bid * D_;
        out = g_qs + (size_t)bid * KTOT;
        act = 1;
    } else if (bid < 6144) {
        int r = bid - 2048;
        in = context + (size_t)r * D_;
        out = g_cs + (size_t)r * KTOT;
        act = 1;
    } else {
        int idx = bid - 6144;
        int w = idx >> 10;
        int r = idx & 1023;
        const float* Ws[4] = {Wq, Wk, Wv, Wo};
        __nv_bfloat16* Os[4];
        Os[0] = g_wqs; Os[1] = g_wks; Os[2] = g_wvs; Os[3] = g_wos;
        in = Ws[w] + (size_t)r * D_;
        out = Os[w] + (size_t)r * KTOT;
        act = 0;
    }
    #pragma unroll
    for (int i = 0; i < 4; i++) {
        int c = threadIdx.x + i * 256;
        float x = in[c];
        __nv_bfloat16 hi = __float2bfloat16(x);
        __nv_bfloat16 lo = __float2bfloat16(x - __bfloat162float(hi));
        if (act) { out[c] = hi; out[D_ + c] = hi; out[2 * D_ + c] = lo; }
        else     { out[c] = hi; out[D_ + c] = lo; out[2 * D_ + c] = hi; }
    }
}

// v_ext_t: fp32 V [b][s][h*64+d] -> bf16 V^T rows [(b*H+h)*64 + d][2S]
__global__ __launch_bounds__(256) void v_ext_t(
    const float* __restrict__ v, __nv_bfloat16* __restrict__ out)
{
    __shared__ float tile[32][33];
    const int s0 = blockIdx.x * 32;
    const int d0 = blockIdx.y * 32;
    const int bh = blockIdx.z;
    const int b = bh / H_;
    const int h = bh % H_;
    const int tx = threadIdx.x, ty = threadIdx.y;
    #pragma unroll
    for (int i = 0; i < 4; i++) {
        int s = s0 + ty + i * 8;
        tile[ty + i * 8][tx] = v[((size_t)(b * S_ + s)) * D_ + h * 64 + d0 + tx];
    }
    __syncthreads();
    #pragma unroll
    for (int i = 0; i < 4; i++) {
        int d = d0 + ty + i * 8;
        float x = tile[tx][ty + i * 8];
        __nv_bfloat16 hi = __float2bfloat16(x);
        __nv_bfloat16 lo = __float2bfloat16(x - __bfloat162float(hi));
        __nv_bfloat16* orow = out + ((size_t)(bh * 64 + d)) * (2 * S_);
        orow[s0 + tx] = hi;
        orow[S_ + s0 + tx] = lo;
    }
}

// ---------------------------------------------------------------------------
// bf16 mma.sync GEMM, templated on MB (M-blocks of 16 per warp).
// Tile: (64*MB) x 128, KB=64 stage, 256 threads = 4 M-warps x 2 N-warps.
// emode 0: C fp32. emode 1: qe ext [hi|hi|lo]. emode 2: ke ext [hi|lo|hi].
// ---------------------------------------------------------------------------
template <int MB>
__global__ __launch_bounds__(256) void gemm_bf16_mma(
    const __nv_bfloat16* __restrict__ A, const __nv_bfloat16* __restrict__ W,
    float* __restrict__ C, __nv_bfloat16* __restrict__ eout,
    int N, int emode, int Lrows)
{
    constexpr int BM = 64 * MB;
    constexpr int ASTAGE = BM * GPITCH;
    constexpr int STAGE = ASTAGE + WSTAGE;

    extern __shared__ char gsm[];
    const uint32_t smb = smem_u32(gsm);

    const int tid = threadIdx.x;
    const int wid = tid >> 5;
    const int lane = tid & 31;
    const int wm = wid & 3;
    const int wn = wid >> 2;
    const int bm = blockIdx.y * BM;
    const int bn = blockIdx.x * GTN;

    // loader mappings
    // A: BM rows, 256 threads -> (256/BM) threads per row
    const int a_lrow = (MB == 2) ? (tid >> 1) : tid;
    const int a_lhalf = (MB == 2) ? (tid & 1) : 0;
    constexpr int A_CH = (MB == 2) ? 4 : 8;       // 16B chunks per thread
    // W: 128 rows, 2 threads per row
    const int w_lrow = tid >> 1;
    const int w_lhalf = tid & 1;

    const __nv_bfloat16* Ag = A + (size_t)(bm + a_lrow) * KTOT + a_lhalf * 32;
    const __nv_bfloat16* Wg = W + (size_t)(bn + w_lrow) * KTOT + w_lhalf * 32;
    const uint32_t a_lsm = a_lrow * GPITCH + a_lhalf * 64;
    const uint32_t w_lsm = w_lrow * GPITCH + w_lhalf * 64;

    float acc[MB][8][4];
    #pragma unroll
    for (int mb = 0; mb < MB; mb++)
        #pragma unroll
        for (int nb = 0; nb < 8; nb++)
            #pragma unroll
            for (int i = 0; i < 4; i++) acc[mb][nb][i] = 0.f;

    const uint32_t a_row = wm * (16 * MB) + (lane & 15);
    const uint32_t a_koff = (lane >> 4) * 16;
    const uint32_t b_row = wn * 64 + (lane & 7) + 8 * ((lane >> 4) & 1);
    const uint32_t b_koff = ((lane >> 3) & 1) * 16;

    // prologue: stages 0,1
    #pragma unroll
    for (int st = 0; st < 2; st++) {
        const uint32_t ab = smb + st * STAGE;
        #pragma unroll
        for (int j = 0; j < A_CH; j++)
            CP_ASYNC16(ab + a_lsm + j * 16, Ag + st * KB2 + j * 8);
        #pragma unroll
        for (int j = 0; j < 4; j++)
            CP_ASYNC16(ab + ASTAGE + w_lsm + j * 16, Wg + st * KB2 + j * 8);
        CP_COMMIT();
    }

    for (int c = 0; c < NITER2; c++) {
        const int buf = c & 1;
        CP_WAIT1();
        __syncthreads();

        const uint32_t ab = smb + buf * STAGE;
        const uint32_t bb = ab + ASTAGE;

        #pragma unroll
        for (int kk = 0; kk < 4; kk++) {
            uint32_t aF[MB][4], bF[8][2];
            #pragma unroll
            for (int mb = 0; mb < MB; mb++) {
                uint32_t addr = ab + (a_row + mb * 16) * GPITCH + kk * 32 + a_koff;
                LDMATRIX_X4(aF[mb][0], aF[mb][1], aF[mb][2], aF[mb][3], addr);
            }
            #pragma unroll
            for (int nb2 = 0; nb2 < 4; nb2++) {
                uint32_t addr = bb + (b_row + nb2 * 16) * GPITCH + kk * 32 + b_koff;
                LDMATRIX_X4(bF[nb2 * 2][0], bF[nb2 * 2][1],
                            bF[nb2 * 2 + 1][0], bF[nb2 * 2 + 1][1], addr);
            }
            #pragma unroll
            for (int mb = 0; mb < MB; mb++)
                #pragma unroll
                for (int nb = 0; nb < 8; nb++)
                    MMA16816(acc[mb][nb][0], acc[mb][nb][1],
                             acc[mb][nb][2], acc[mb][nb][3],
                             aF[mb][0], aF[mb][1], aF[mb][2], aF[mb][3],
                             bF[nb][0], bF[nb][1]);
        }

        __syncthreads();
        if (c + 2 < NITER2) {
            const uint32_t pb = smb + buf * STAGE;
            #pragma unroll
            for (int j = 0; j < A_CH; j++)
                CP_ASYNC16(pb + a_lsm + j * 16, Ag + (c + 2) * KB2 + j * 8);
            #pragma unroll
            for (int j = 0; j < 4; j++)
                CP_ASYNC16(pb + ASTAGE + w_lsm + j * 16, Wg + (c + 2) * KB2 + j * 8);
        }
        CP_COMMIT();
    }
    CP_WAIT0();

    const int gr = lane >> 2;
    const int gc = (lane & 3) * 2;

    if (emode == 0) {
        #pragma unroll
        for (int mb = 0; mb < MB; mb++) {
            const int row0 = bm + wm * (16 * MB) + mb * 16 + gr;
            #pragma unroll
            for (int nb = 0; nb < 8; nb++) {
                const int col = bn + wn * 64 + nb * 8 + gc;
                *(float2*)&C[(size_t)row0 * N + col] =
                    make_float2(acc[mb][nb][0], acc[mb][nb][1]);
                *(float2*)&C[(size_t)(row0 + 8) * N + col] =
                    make_float2(acc[mb][nb][2], acc[mb][nb][3]);
            }
        }
    } else {
        #pragma unroll
        for (int mb = 0; mb < MB; mb++) {
            #pragma unroll
            for (int half = 0; half < 2; half++) {
                const int row = bm + wm * (16 * MB) + mb * 16 + gr + half * 8;
                const int b = row / Lrows;
                const int t = row % Lrows;
                #pragma unroll
                for (int nb = 0; nb < 8; nb++) {
                    const int col = bn + wn * 64 + nb * 8 + gc;
                    const int h = col >> 6;
                    const int dd = col & 63;
                    float x0 = acc[mb][nb][half * 2];
                    float x1 = acc[mb][nb][half * 2 + 1];
                    __nv_bfloat16 h0 = __float2bfloat16(x0);
                    __nv_bfloat16 h1 = __float2bfloat16(x1);
                    __nv_bfloat16 l0 = __float2bfloat16(x0 - __bfloat162float(h0));
                    __nv_bfloat16 l1 = __float2bfloat16(x1 - __bfloat162float(h1));
                    __nv_bfloat16* orow =
                        eout + ((size_t)(b * H_ + h) * Lrows + t) * AKE;
                    __nv_bfloat162 hv; hv.x = h0; hv.y = h1;
                    __nv_bfloat162 lv; lv.x = l0; lv.y = l1;
                    if (emode == 1) {
                        *(__nv_bfloat162*)&orow[dd] = hv;
                        *(__nv_bfloat162*)&orow[64 + dd] = hv;
                        *(__nv_bfloat162*)&orow[128 + dd] = lv;
                    } else {
                        *(__nv_bfloat162*)&orow[dd] = hv;
                        *(__nv_bfloat162*)&orow[64 + dd] = lv;
                        *(__nv_bfloat162*)&orow[128 + dd] = hv;
                    }
                }
            }
        }
    }
}

// ---------------------------------------------------------------------------
// Tensor-core flash attention (unchanged from R10, validated).
// ---------------------------------------------------------------------------
__global__ __launch_bounds__(256) void attn_mma(
    const __nv_bfloat16* __restrict__ qe,
    const __nv_bfloat16* __restrict__ ke,
    const __nv_bfloat16* __restrict__ vte)
{
    extern __shared__ char smraw[];
    const uint32_t sQ = smem_u32(smraw);
    const uint32_t sK = sQ + AM * APB;
    const uint32_t sV = sK + 64 * APB;

    const int tid = threadIdx.x;
    const int wid = tid >> 5;
    const int lane = tid & 31;
    const int hb = blockIdx.z;
    const int split = blockIdx.y;
    const int t0 = blockIdx.x * AM;
    const int h = hb % H_;

    const float slope = exp2f(-(float)(h + 1) / 16.0f);
    const size_t qrow0 = (size_t)hb * T_ + t0;
    const size_t krow0 = (size_t)hb * S_;
    const size_t vrow0 = (size_t)hb * 64;

    for (int idx = tid; idx < AM * 24; idx += 256) {
        int r = idx / 24, c = idx % 24;
        CP_ASYNC16(sQ + r * APB + c * 16, qe + (qrow0 + r) * AKE + c * 8);
    }
    CP_COMMIT();

    float sc[8][4], oF[8][4];
    #pragma unroll
    for (int nb = 0; nb < 8; nb++)
        #pragma unroll
        for (int i = 0; i < 4; i++) oF[nb][i] = 0.f;
    float m0 = -INFINITY, m1 = -INFINITY, l0 = 0.f, l1 = 0.f;

    const int r0 = lane >> 2;
    const float trow0 = (float)(t0 + wid * 16 + r0);
    const float trow1 = trow0 + 8.0f;

    const uint32_t a_addr_base = sQ + (wid * 16 + (lane & 15)) * APB + (lane >> 4) * 16;
    const uint32_t b_row = (lane & 7) + 8 * ((lane >> 4) & 1);
    const uint32_t b_koff = ((lane >> 3) & 1) * 16;

    const int sbeg = split * SPS;
    const int send = sbeg + SPS;

    for (int s0 = sbeg; s0 < send; s0 += 64) {
        for (int idx = tid; idx < 64 * 24; idx += 256) {
            int r = idx / 24, c = idx % 24;
            CP_ASYNC16(sK + r * APB + c * 16, ke + (krow0 + s0 + r) * AKE + c * 8);
        }
        for (int idx = tid; idx < 64 * 24; idx += 256) {
            int r = idx / 24, c = idx % 24;
            const __nv_bfloat16* vb = vte + (vrow0 + r) * (size_t)(2 * S_);
            const __nv_bfloat16* src =
                (c < 8) ? vb + s0 + c * 8
                        : (c < 16 ? vb + S_ + s0 + (c - 8) * 8
                                  : vb + s0 + (c - 16) * 8);
            CP_ASYNC16(sV + r * APB + c * 16, src);
        }
        CP_COMMIT();
        CP_WAIT0();
        __syncthreads();

        #pragma unroll
        for (int nb = 0; nb < 8; nb++)
            #pragma unroll
            for (int i = 0; i < 4; i++) sc[nb][i] = 0.f;

        #pragma unroll
        for (int ks = 0; ks < 12; ks++) {
            uint32_t aF[4], bF[8][2];
            LDMATRIX_X4(aF[0], aF[1], aF[2], aF[3], a_addr_base + ks * 32);
            #pragma unroll
            for (int nb2 = 0; nb2 < 4; nb2++) {
                uint32_t addr = sK + (b_row + nb2 * 16) * APB + ks * 32 + b_koff;
                LDMATRIX_X4(bF[nb2 * 2][0], bF[nb2 * 2][1],
                            bF[nb2 * 2 + 1][0], bF[nb2 * 2 + 1][1], addr);
            }
            #pragma unroll
            for (int nb = 0; nb < 8; nb++)
                MMA16816(sc[nb][0], sc[nb][1], sc[nb][2], sc[nb][3],
                         aF[0], aF[1], aF[2], aF[3], bF[nb][0], bF[nb][1]);
        }

        float tm0 = -INFINITY, tm1 = -INFINITY;
        #pragma unroll
        for (int nb = 0; nb < 8; nb++) {
            float scol = (float)(s0 + nb * 8 + 2 * (lane & 3));
            sc[nb][0] = sc[nb][0] * SCALE_ - slope * fabsf(trow0 - scol);
            sc[nb][1] = sc[nb][1] * SCALE_ - slope * fabsf(trow0 - (scol + 1.f));
            sc[nb][2] = sc[nb][2] * SCALE_ - slope * fabsf(trow1 - scol);
            sc[nb][3] = sc[nb][3] * SCALE_ - slope * fabsf(trow1 - (scol + 1.f));
            tm0 = fmaxf(tm0, fmaxf(sc[nb][0], sc[nb][1]));
            tm1 = fmaxf(tm1, fmaxf(sc[nb][2], sc[nb][3]));
        }
        tm0 = fmaxf(tm0, __shfl_xor_sync(0xffffffffu, tm0, 1));
        tm0 = fmaxf(tm0, __shfl_xor_sync(0xffffffffu, tm0, 2));
        tm1 = fmaxf(tm1, __shfl_xor_sync(0xffffffffu, tm1, 1));
        tm1 = fmaxf(tm1, __shfl_xor_sync(0xffffffffu, tm1, 2));

        float mn0 = fmaxf(m0, tm0);
        float mn1 = fmaxf(m1, tm1);
        float cr0 = __expf(m0 - mn0);
        float cr1 = __expf(m1 - mn1);
        l0 *= cr0; l1 *= cr1;
        #pragma unroll
        for (int nb = 0; nb < 8; nb++) {
            oF[nb][0] *= cr0; oF[nb][1] *= cr0;
            oF[nb][2] *= cr1; oF[nb][3] *= cr1;
        }

        float rs0 = 0.f, rs1 = 0.f;
        #pragma unroll
        for (int nb = 0; nb < 8; nb++) {
            sc[nb][0] = __expf(sc[nb][0] - mn0);
            sc[nb][1] = __expf(sc[nb][1] - mn0);
            sc[nb][2] = __expf(sc[nb][2] - mn1);
            sc[nb][3] = __expf(sc[nb][3] - mn1);
            rs0 += sc[nb][0] + sc[nb][1];
            rs1 += sc[nb][2] + sc[nb][3];
        }
        rs0 += __shfl_xor_sync(0xffffffffu, rs0, 1);
        rs0 += __shfl_xor_sync(0xffffffffu, rs0, 2);
        rs1 += __shfl_xor_sync(0xffffffffu, rs1, 1);
        rs1 += __shfl_xor_sync(0xffffffffu, rs1, 2);
        l0 += rs0; l1 += rs1;
        m0 = mn0; m1 = mn1;

        uint32_t phi[4][4];
        #pragma unroll
        for (int ks = 0; ks < 4; ks++) {
            phi[ks][0] = pack_bf16x2(sc[2 * ks][0], sc[2 * ks][1]);
            phi[ks][1] = pack_bf16x2(sc[2 * ks][2], sc[2 * ks][3]);
            phi[ks][2] = pack_bf16x2(sc[2 * ks + 1][0], sc[2 * ks + 1][1]);
            phi[ks][3] = pack_bf16x2(sc[2 * ks + 1][2], sc[2 * ks + 1][3]);
        }

        #pragma unroll
        for (int ks = 0; ks < 12; ks++) {
            uint32_t bF[8][2];
            #pragma unroll
            for (int nb2 = 0; nb2 < 4; nb2++) {
                uint32_t addr = sV + (b_row + nb2 * 16) * APB + ks * 32 + b_koff;
                LDMATRIX_X4(bF[nb2 * 2][0], bF[nb2 * 2][1],
                            bF[nb2 * 2 + 1][0], bF[nb2 * 2 + 1][1], addr);
            }
            uint32_t aP[4];
            if (ks < 8) {
                const int kk = ks & 3;
                aP[0] = phi[kk][0]; aP[1] = phi[kk][1];
                aP[2] = phi[kk][2]; aP[3] = phi[kk][3];
            } else {
                const int kk = ks - 8;
                #pragma unroll
                for (int j = 0; j < 4; j++) {
                    const int nb = 2 * kk + (j >> 1);
                    const int ci = (j & 1) * 2;
                    float pe = sc[nb][ci]     - bf16lo_f(phi[kk][j]);
                    float po = sc[nb][ci + 1] - bf16hi_f(phi[kk][j]);
                    aP[j] = pack_bf16x2(pe, po);
                }
            }
            #pragma unroll
            for (int nb = 0; nb < 8; nb++)
                MMA16816(oF[nb][0], oF[nb][1], oF[nb][2], oF[nb][3],
                         aP[0], aP[1], aP[2], aP[3], bF[nb][0], bF[nb][1]);
        }
        __syncthreads();
    }

    const size_t base = (size_t)(split * B_ * H_ + hb) * T_;
    const size_t pidx0 = base + t0 + wid * 16 + r0;
    const size_t pidx1 = pidx0 + 8;
    #pragma unroll
    for (int nb = 0; nb < 8; nb++) {
        const int col = nb * 8 + 2 * (lane & 3);
        *(float2*)&g_pacc[pidx0 * HD_ + col] = make_float2(oF[nb][0], oF[nb][1]);
        *(float2*)&g_pacc[pidx1 * HD_ + col] = make_float2(oF[nb][2], oF[nb][3]);
    }
    if ((lane & 3) == 0) {
        g_pm[pidx0] = m0; g_pl[pidx0] = l0;
        g_pm[pidx1] = m1; g_pl[pidx1] = l1;
    }
}

// ---------------------------------------------------------------------------
// Combine split-KV partials -> split-act layout [b*T+t][hi|hi|lo] (g_as)
// ---------------------------------------------------------------------------
__global__ __launch_bounds__(256) void attn_combine_kernel(
    __nv_bfloat16* __restrict__ as_out)
{
    const int d = threadIdx.x & 63;
    const int rlocal = threadIdx.x >> 6;
    const size_t row = (size_t)blockIdx.x * 4 + rlocal;
    const int t = row % T_;
    const int h = (row / T_) % H_;
    const int b = row / ((size_t)T_ * H_);

    float m0 = g_pm[row];
    float l0 = g_pl[row];
    float m1 = g_pm[(size_t)B_ * H_ * T_ + row];
    float l1 = g_pl[(size_t)B_ * H_ * T_ + row];

    float M = fmaxf(m0, m1);
    float e0 = __expf(m0 - M), e1 = __expf(m1 - M);
    float L = l0 * e0 + l1 * e1;
    float inv = 1.f / L;

    float a0 = g_pacc[row * HD_ + d];
    float a1 = g_pacc[((size_t)B_ * H_ * T_ + row) * HD_ + d];
    float val = (a0 * e0 + a1 * e1) * inv;

    __nv_bfloat16 hi = __float2bfloat16(val);
    __nv_bfloat16 lo = __float2bfloat16(val - __bfloat162float(hi));
    const int c = h * 64 + d;
    __nv_bfloat16* orow = as_out + ((size_t)(b * T_ + t)) * KTOT;
    orow[c] = hi; orow[D_ + c] = hi; orow[2 * D_ + c] = lo;
}

// ---------------------------------------------------------------------------
// residual + RMSNorm
// ---------------------------------------------------------------------------
__global__ __launch_bounds__(256) void rms_kernel(
    const float* __restrict__ query, const float* __restrict__ proj,
    const float* __restrict__ w, float* __restrict__ out)
{
    __shared__ float sh[8];
    __shared__ float s_inv;
    const size_t row = blockIdx.x;
    const float* qr = query + row * D_;
    const float* pr = proj + row * D_;
    float* orow = out + row * D_;

    float x[4];
    float ss = 0.f;
    #pragma unroll
    for (int i = 0; i < 4; i++) {
        int idx = threadIdx.x + i * 256;
        x[i] = qr[idx] + pr[idx];
        ss += x[i] * x[i];
    }
    #pragma unroll
    for (int ofs = 16; ofs > 0; ofs >>= 1)
        ss += __shfl_xor_sync(0xffffffffu, ss, ofs);
    const int lane = threadIdx.x & 31, wid = threadIdx.x >> 5;
    if (lane == 0) sh[wid] = ss;
    __syncthreads();
    if (threadIdx.x == 0) {
        float tot = 0.f;
        #pragma unroll
        for (int i = 0; i < 8; i++) tot += sh[i];
        s_inv = rsqrtf(tot * (1.0f / D_) + RMS_EPS_);
    }
    __syncthreads();
    const float inv = s_inv;
    #pragma unroll
    for (int i = 0; i < 4; i++) {
        int idx = threadIdx.x + i * 256;
        orow[idx] = x[i] * inv * w[idx];
    }
}

// ---------------------------------------------------------------------------
extern "C" void kernel_launch(void* const* d_in, const int* in_sizes, int n_in,
                              void* d_out, int out_size)
{
    const float* query   = (const float*)d_in[0];
    const float* context = (const float*)d_in[1];
    const float* Wq      = (const float*)d_in[2];
    const float* Wk      = (const float*)d_in[3];
    const float* Wv      = (const float*)d_in[4];
    const float* Wo      = (const float*)d_in[5];
    const float* rmsw    = (const float*)d_in[6];
    float* out = (float*)d_out;

    float *pv, *pproj;
    cudaGetSymbolAddress((void**)&pv,    g_v);
    cudaGetSymbolAddress((void**)&pproj, g_proj);

    __nv_bfloat16 *qs, *cs, *as, *wqs, *wks, *wvs, *wos, *qe, *kke, *vte;
    cudaGetSymbolAddress((void**)&qs,  g_qs);
    cudaGetSymbolAddress((void**)&cs,  g_cs);
    cudaGetSymbolAddress((void**)&as,  g_as);
    cudaGetSymbolAddress((void**)&wqs, g_wqs);
    cudaGetSymbolAddress((void**)&wks, g_wks);
    cudaGetSymbolAddress((void**)&wvs, g_wvs);
    cudaGetSymbolAddress((void**)&wos, g_wos);
    cudaGetSymbolAddress((void**)&qe,  g_qe);
    cudaGetSymbolAddress((void**)&kke, g_ke);
    cudaGetSymbolAddress((void**)&vte, g_vte);

    const int SM2 = 2 * (128 * GPITCH + WSTAGE);   // 73728
    const int SM4 = 2 * (256 * GPITCH + WSTAGE);   // 110592
    cudaFuncSetAttribute(gemm_bf16_mma<2>,
        cudaFuncAttributeMaxDynamicSharedMemorySize, SM2);
    cudaFuncSetAttribute(gemm_bf16_mma<4>,
        cudaFuncAttributeMaxDynamicSharedMemorySize, SM4);
    cudaFuncSetAttribute(attn_mma,
        cudaFuncAttributeMaxDynamicSharedMemorySize, ATTN_SMEM);

    const int MQ = B_ * T_;   // 2048
    const int MK = B_ * S_;   // 4096

    // all input conversions in one launch
    split_all<<<10240, 256>>>(query, context, Wq, Wk, Wv, Wo);

    // projections
    dim3 gq(D_ / GTN, MQ / 128);    // 8 x 16 = 128 CTAs (MB=2)
    dim3 gk(D_ / GTN, MK / 256);    // 8 x 16 = 128 CTAs (MB=4)
    gemm_bf16_mma<2><<<gq, 256, SM2>>>(qs, wqs, nullptr, qe,  D_, 1, T_);
    gemm_bf16_mma<4><<<gk, 256, SM4>>>(cs, wks, nullptr, kke, D_, 2, S_);
    gemm_bf16_mma<4><<<gk, 256, SM4>>>(cs, wvs, pv, nullptr,  D_, 0, 0);

    v_ext_t<<<dim3(S_ / 32, 2, B_ * H_), dim3(32, 8)>>>(pv, vte);

    // tensor-core attention
    attn_mma<<<dim3(T_ / AM, NS_, B_ * H_), 256, ATTN_SMEM>>>(qe, kke, vte);
    attn_combine_kernel<<<(B_ * H_ * T_) / 4, 256>>>(as);

    // output projection
    gemm_bf16_mma<2><<<gq, 256, SM2>>>(as, wos, pproj, nullptr, D_, 0, 0);

    rms_kernel<<<MQ, 256>>>(query, pproj, rmsw, out);
}

// round 12
// speedup vs baseline: 1.0068x; 1.0068x over previous
#include <cuda_runtime.h>
#include <cuda_bf16.h>
#include <math.h>
#include <stdint.h>

// Problem constants
#define B_  2
#define T_  1024
#define S_  2048
#define D_  1024
#define H_  16
#define HD_ 64
#define SCALE_ 0.125f
#define RMS_EPS_ 1e-6f

#define NS_ 2
#define SPS (S_ / NS_)

// bf16-split GEMM config
#define KTOT (3 * D_)
#define KB2 64                    // bf16 K per stage
#define NITER2 (KTOT / KB2)       // 48
#define GTN 128
#define GPITCH 144                // smem row pitch bytes (64 bf16 + pad)
#define WSTAGE (128 * GPITCH)     // W stage bytes

// attention mma config
#define AM 128           // query rows per CTA (8 warps x 16)
#define AKE 192          // extended K dim (3 x 64)
#define APB 400          // smem row pitch bytes
#define ATTN_SMEM ((AM + 64 + 64) * APB)  // 102400

// Scratch (device globals; no allocation allowed)
__device__ float g_v[B_ * S_ * D_];
__device__ float g_proj[B_ * T_ * D_];
__device__ float g_pacc[NS_ * B_ * H_ * T_ * HD_];
__device__ float g_pm[NS_ * B_ * H_ * T_];
__device__ float g_pl[NS_ * B_ * H_ * T_];
// bf16 split operands (projection GEMMs)
__device__ __nv_bfloat16 g_qs[(size_t)B_ * T_ * KTOT];
__device__ __nv_bfloat16 g_cs[(size_t)B_ * S_ * KTOT];
__device__ __nv_bfloat16 g_as[(size_t)B_ * T_ * KTOT];
__device__ __nv_bfloat16 g_wqs[(size_t)D_ * KTOT];
__device__ __nv_bfloat16 g_wks[(size_t)D_ * KTOT];
__device__ __nv_bfloat16 g_wvs[(size_t)D_ * KTOT];
__device__ __nv_bfloat16 g_wos[(size_t)D_ * KTOT];
// attention extended operands
__device__ __nv_bfloat16 g_qe[(size_t)B_ * H_ * T_ * AKE];        // [qhi|qhi|qlo]
__device__ __nv_bfloat16 g_ke[(size_t)B_ * H_ * S_ * AKE];        // [khi|klo|khi]
__device__ __nv_bfloat16 g_vte[(size_t)B_ * H_ * HD_ * 2 * S_];   // V^T [d][vhi(S)|vlo(S)]

// ============================ PTX helpers (base ISA) ========================
__device__ __forceinline__ uint32_t smem_u32(const void* p) {
    uint32_t a;
    asm("{ .reg .u64 t; cvta.to.shared.u64 t, %1; cvt.u32.u64 %0, t; }"
        : "=r"(a) : "l"(p));
    return a;
}

#define CP_ASYNC16(dst_u32, src_ptr) \
    asm volatile("cp.async.cg.shared.global [%0], [%1], 16;" \
        :: "r"(dst_u32), "l"(src_ptr))
#define CP_COMMIT() asm volatile("cp.async.commit_group;" ::: "memory")
#define CP_WAIT2()  asm volatile("cp.async.wait_group 2;" ::: "memory")
#define CP_WAIT0()  asm volatile("cp.async.wait_group 0;" ::: "memory")

#define LDMATRIX_X4(r0, r1, r2, r3, addr) \
    asm volatile("ldmatrix.sync.aligned.m8n8.x4.shared.b16 {%0,%1,%2,%3}, [%4];" \
        : "=r"(r0), "=r"(r1), "=r"(r2), "=r"(r3) : "r"(addr))

#define MMA16816(d0, d1, d2, d3, a0, a1, a2, a3, b0, b1) \
    asm volatile("mma.sync.aligned.m16n8k16.row.col.f32.bf16.bf16.f32 " \
        "{%0,%1,%2,%3}, {%4,%5,%6,%7}, {%8,%9}, {%0,%1,%2,%3};" \
        : "+f"(d0), "+f"(d1), "+f"(d2), "+f"(d3) \
        : "r"(a0), "r"(a1), "r"(a2), "r"(a3), "r"(b0), "r"(b1))

__device__ __forceinline__ uint32_t pack_bf16x2(float p0, float p1) {
    uint32_t d;
    asm("cvt.rn.bf16x2.f32 %0, %1, %2;" : "=r"(d) : "f"(p1), "f"(p0));
    return d;
}
__device__ __forceinline__ float bf16lo_f(uint32_t u) {
    return __uint_as_float(u << 16);
}
__device__ __forceinline__ float bf16hi_f(uint32_t u) {
    return __uint_as_float(u & 0xffff0000u);
}

// ---------------------------------------------------------------------------
// Mega split kernel: all input conversions in one launch.
// ---------------------------------------------------------------------------
__global__ __launch_bounds__(256) void split_all(
    const float* __restrict__ query, const float* __restrict__ context,
    const float* __restrict__ Wq, const float* __restrict__ Wk,
    const float* __restrict__ Wv, const float* __restrict__ Wo)
{
    const int bid = blockIdx.x;
    const float* in;
    __nv_bfloat16* out;
    int act;
    if (bid < 2048) {
        in = query + (size_t)bid * D_;
        out = g_qs + (size_t)bid * KTOT;
        act = 1;
    } else if (bid < 6144) {
        int r = bid - 2048;
        in = context + (size_t)r * D_;
        out = g_cs + (size_t)r * KTOT;
        act = 1;
    } else {
        int idx = bid - 6144;
        int w = idx >> 10;
        int r = idx & 1023;
        const float* Ws[4] = {Wq, Wk, Wv, Wo};
        __nv_bfloat16* Os[4];
        Os[0] = g_wqs; Os[1] = g_wks; Os[2] = g_wvs; Os[3] = g_wos;
        in = Ws[w] + (size_t)r * D_;
        out = Os[w] + (size_t)r * KTOT;
        act = 0;
    }
    #pragma unroll
    for (int i = 0; i < 4; i++) {
        int c = threadIdx.x + i * 256;
        float x = in[c];
        __nv_bfloat16 hi = __float2bfloat16(x);
        __nv_bfloat16 lo = __float2bfloat16(x - __bfloat162float(hi));
        if (act) { out[c] = hi; out[D_ + c] = hi; out[2 * D_ + c] = lo; }
        else     { out[c] = hi; out[D_ + c] = lo; out[2 * D_ + c] = hi; }
    }
}

// v_ext_t: fp32 V [b][s][h*64+d] -> bf16 V^T rows [(b*H+h)*64 + d][2S]
__global__ __launch_bounds__(256) void v_ext_t(
    const float* __restrict__ v, __nv_bfloat16* __restrict__ out)
{
    __shared__ float tile[32][33];
    const int s0 = blockIdx.x * 32;
    const int d0 = blockIdx.y * 32;
    const int bh = blockIdx.z;
    const int b = bh / H_;
    const int h = bh % H_;
    const int tx = threadIdx.x, ty = threadIdx.y;
    #pragma unroll
    for (int i = 0; i < 4; i++) {
        int s = s0 + ty + i * 8;
        tile[ty + i * 8][tx] = v[((size_t)(b * S_ + s)) * D_ + h * 64 + d0 + tx];
    }
    __syncthreads();
    #pragma unroll
    for (int i = 0; i < 4; i++) {
        int d = d0 + ty + i * 8;
        float x = tile[tx][ty + i * 8];
        __nv_bfloat16 hi = __float2bfloat16(x);
        __nv_bfloat16 lo = __float2bfloat16(x - __bfloat162float(hi));
        __nv_bfloat16* orow = out + ((size_t)(bh * 64 + d)) * (2 * S_);
        orow[s0 + tx] = hi;
        orow[S_ + s0 + tx] = lo;
    }
}

// ---------------------------------------------------------------------------
// bf16 mma.sync GEMM, templated on MB. Tile (64*MB) x 128, KB=64 stage.
// 4-buffer / 3-in-flight cp.async ring, ONE __syncthreads per stage.
// emode 0: C fp32. emode 1: qe ext [hi|hi|lo]. emode 2: ke ext [hi|lo|hi].
// ---------------------------------------------------------------------------
template <int MB>
__global__ __launch_bounds__(256) void gemm_bf16_mma(
    const __nv_bfloat16* __restrict__ A, const __nv_bfloat16* __restrict__ W,
    float* __restrict__ C, __nv_bfloat16* __restrict__ eout,
    int N, int emode, int Lrows)
{
    constexpr int BM = 64 * MB;
    constexpr int ASTAGE = BM * GPITCH;
    constexpr int STAGE = ASTAGE + WSTAGE;

    extern __shared__ char gsm[];
    const uint32_t smb = smem_u32(gsm);

    const int tid = threadIdx.x;
    const int wid = tid >> 5;
    const int lane = tid & 31;
    const int wm = wid & 3;
    const int wn = wid >> 2;
    const int bm = blockIdx.y * BM;
    const int bn = blockIdx.x * GTN;

    // loader mappings
    const int a_lrow = (MB == 2) ? (tid >> 1) : tid;
    const int a_lhalf = (MB == 2) ? (tid & 1) : 0;
    constexpr int A_CH = (MB == 2) ? 4 : 8;
    const int w_lrow = tid >> 1;
    const int w_lhalf = tid & 1;

    const __nv_bfloat16* Ag = A + (size_t)(bm + a_lrow) * KTOT + a_lhalf * 32;
    const __nv_bfloat16* Wg = W + (size_t)(bn + w_lrow) * KTOT + w_lhalf * 32;
    const uint32_t a_lsm = a_lrow * GPITCH + a_lhalf * 64;
    const uint32_t w_lsm = w_lrow * GPITCH + w_lhalf * 64;

    float acc[MB][8][4];
    #pragma unroll
    for (int mb = 0; mb < MB; mb++)
        #pragma unroll
        for (int nb = 0; nb < 8; nb++)
            #pragma unroll
            for (int i = 0; i < 4; i++) acc[mb][nb][i] = 0.f;

    const uint32_t a_row = wm * (16 * MB) + (lane & 15);
    const uint32_t a_koff = (lane >> 4) * 16;
    const uint32_t b_row = wn * 64 + (lane & 7) + 8 * ((lane >> 4) & 1);
    const uint32_t b_koff = ((lane >> 3) & 1) * 16;

    // prologue: stages 0,1,2
    #pragma unroll
    for (int st = 0; st < 3; st++) {
        const uint32_t ab = smb + st * STAGE;
        #pragma unroll
        for (int j = 0; j < A_CH; j++)
            CP_ASYNC16(ab + a_lsm + j * 16, Ag + st * KB2 + j * 8);
        #pragma unroll
        for (int j = 0; j < 4; j++)
            CP_ASYNC16(ab + ASTAGE + w_lsm + j * 16, Wg + st * KB2 + j * 8);
        CP_COMMIT();
    }

    for (int c = 0; c < NITER2; c++) {
        const int buf = c & 3;
        CP_WAIT2();          // stage c complete (<=2 younger groups pending)
        __syncthreads();     // everyone done reading stage c-1's buffer

        // issue stage c+3 into buffer (c+3)&3 == (c-1)&3 (drained by the bar)
        if (c + 3 < NITER2) {
            const uint32_t pb = smb + ((c + 3) & 3) * STAGE;
            #pragma unroll
            for (int j = 0; j < A_CH; j++)
                CP_ASYNC16(pb + a_lsm + j * 16, Ag + (c + 3) * KB2 + j * 8);
            #pragma unroll
            for (int j = 0; j < 4; j++)
                CP_ASYNC16(pb + ASTAGE + w_lsm + j * 16, Wg + (c + 3) * KB2 + j * 8);
        }
        CP_COMMIT();         // exactly one group per iteration

        const uint32_t ab = smb + buf * STAGE;
        const uint32_t bb = ab + ASTAGE;

        #pragma unroll
        for (int kk = 0; kk < 4; kk++) {
            uint32_t aF[MB][4], bF[8][2];
            #pragma unroll
            for (int mb = 0; mb < MB; mb++) {
                uint32_t addr = ab + (a_row + mb * 16) * GPITCH + kk * 32 + a_koff;
                LDMATRIX_X4(aF[mb][0], aF[mb][1], aF[mb][2], aF[mb][3], addr);
            }
            #pragma unroll
            for (int nb2 = 0; nb2 < 4; nb2++) {
                uint32_t addr = bb + (b_row + nb2 * 16) * GPITCH + kk * 32 + b_koff;
                LDMATRIX_X4(bF[nb2 * 2][0], bF[nb2 * 2][1],
                            bF[nb2 * 2 + 1][0], bF[nb2 * 2 + 1][1], addr);
            }
            #pragma unroll
            for (int mb = 0; mb < MB; mb++)
                #pragma unroll
                for (int nb = 0; nb < 8; nb++)
                    MMA16816(acc[mb][nb][0], acc[mb][nb][1],
                             acc[mb][nb][2], acc[mb][nb][3],
                             aF[mb][0], aF[mb][1], aF[mb][2], aF[mb][3],
                             bF[nb][0], bF[nb][1]);
        }
    }
    CP_WAIT0();

    const int gr = lane >> 2;
    const int gc = (lane & 3) * 2;

    if (emode == 0) {
        #pragma unroll
        for (int mb = 0; mb < MB; mb++) {
            const int row0 = bm + wm * (16 * MB) + mb * 16 + gr;
            #pragma unroll
            for (int nb = 0; nb < 8; nb++) {
                const int col = bn + wn * 64 + nb * 8 + gc;
                *(float2*)&C[(size_t)row0 * N + col] =
                    make_float2(acc[mb][nb][0], acc[mb][nb][1]);
                *(float2*)&C[(size_t)(row0 + 8) * N + col] =
                    make_float2(acc[mb][nb][2], acc[mb][nb][3]);
            }
        }
    } else {
        #pragma unroll
        for (int mb = 0; mb < MB; mb++) {
            #pragma unroll
            for (int half = 0; half < 2; half++) {
                const int row = bm + wm * (16 * MB) + mb * 16 + gr + half * 8;
                const int b = row / Lrows;
                const int t = row % Lrows;
                #pragma unroll
                for (int nb = 0; nb < 8; nb++) {
                    const int col = bn + wn * 64 + nb * 8 + gc;
                    const int h = col >> 6;
                    const int dd = col & 63;
                    float x0 = acc[mb][nb][half * 2];
                    float x1 = acc[mb][nb][half * 2 + 1];
                    __nv_bfloat16 h0 = __float2bfloat16(x0);
                    __nv_bfloat16 h1 = __float2bfloat16(x1);
                    __nv_bfloat16 l0 = __float2bfloat16(x0 - __bfloat162float(h0));
                    __nv_bfloat16 l1 = __float2bfloat16(x1 - __bfloat162float(h1));
                    __nv_bfloat16* orow =
                        eout + ((size_t)(b * H_ + h) * Lrows + t) * AKE;
                    __nv_bfloat162 hv; hv.x = h0; hv.y = h1;
                    __nv_bfloat162 lv; lv.x = l0; lv.y = l1;
                    if (emode == 1) {
                        *(__nv_bfloat162*)&orow[dd] = hv;
                        *(__nv_bfloat162*)&orow[64 + dd] = hv;
                        *(__nv_bfloat162*)&orow[128 + dd] = lv;
                    } else {
                        *(__nv_bfloat162*)&orow[dd] = hv;
                        *(__nv_bfloat162*)&orow[64 + dd] = lv;
                        *(__nv_bfloat162*)&orow[128 + dd] = hv;
                    }
                }
            }
        }
    }
}

// ---------------------------------------------------------------------------
// Tensor-core flash attention (unchanged, validated).
// ---------------------------------------------------------------------------
__global__ __launch_bounds__(256) void attn_mma(
    const __nv_bfloat16* __restrict__ qe,
    const __nv_bfloat16* __restrict__ ke,
    const __nv_bfloat16* __restrict__ vte)
{
    extern __shared__ char smraw[];
    const uint32_t sQ = smem_u32(smraw);
    const uint32_t sK = sQ + AM * APB;
    const uint32_t sV = sK + 64 * APB;

    const int tid = threadIdx.x;
    const int wid = tid >> 5;
    const int lane = tid & 31;
    const int hb = blockIdx.z;
    const int split = blockIdx.y;
    const int t0 = blockIdx.x * AM;
    const int h = hb % H_;

    const float slope = exp2f(-(float)(h + 1) / 16.0f);
    const size_t qrow0 = (size_t)hb * T_ + t0;
    const size_t krow0 = (size_t)hb * S_;
    const size_t vrow0 = (size_t)hb * 64;

    for (int idx = tid; idx < AM * 24; idx += 256) {
        int r = idx / 24, c = idx % 24;
        CP_ASYNC16(sQ + r * APB + c * 16, qe + (qrow0 + r) * AKE + c * 8);
    }
    CP_COMMIT();

    float sc[8][4], oF[8][4];
    #pragma unroll
    for (int nb = 0; nb < 8; nb++)
        #pragma unroll
        for (int i = 0; i < 4; i++) oF[nb][i] = 0.f;
    float m0 = -INFINITY, m1 = -INFINITY, l0 = 0.f, l1 = 0.f;

    const int r0 = lane >> 2;
    const float trow0 = (float)(t0 + wid * 16 + r0);
    const float trow1 = trow0 + 8.0f;

    const uint32_t a_addr_base = sQ + (wid * 16 + (lane & 15)) * APB + (lane >> 4) * 16;
    const uint32_t b_row = (lane & 7) + 8 * ((lane >> 4) & 1);
    const uint32_t b_koff = ((lane >> 3) & 1) * 16;

    const int sbeg = split * SPS;
    const int send = sbeg + SPS;

    for (int s0 = sbeg; s0 < send; s0 += 64) {
        for (int idx = tid; idx < 64 * 24; idx += 256) {
            int r = idx / 24, c = idx % 24;
            CP_ASYNC16(sK + r * APB + c * 16, ke + (krow0 + s0 + r) * AKE + c * 8);
        }
        for (int idx = tid; idx < 64 * 24; idx += 256) {
            int r = idx / 24, c = idx % 24;
            const __nv_bfloat16* vb = vte + (vrow0 + r) * (size_t)(2 * S_);
            const __nv_bfloat16* src =
                (c < 8) ? vb + s0 + c * 8
                        : (c < 16 ? vb + S_ + s0 + (c - 8) * 8
                                  : vb + s0 + (c - 16) * 8);
            CP_ASYNC16(sV + r * APB + c * 16, src);
        }
        CP_COMMIT();
        CP_WAIT0();
        __syncthreads();

        #pragma unroll
        for (int nb = 0; nb < 8; nb++)
            #pragma unroll
            for (int i = 0; i < 4; i++) sc[nb][i] = 0.f;

        #pragma unroll
        for (int ks = 0; ks < 12; ks++) {
            uint32_t aF[4], bF[8][2];
            LDMATRIX_X4(aF[0], aF[1], aF[2], aF[3], a_addr_base + ks * 32);
            #pragma unroll
            for (int nb2 = 0; nb2 < 4; nb2++) {
                uint32_t addr = sK + (b_row + nb2 * 16) * APB + ks * 32 + b_koff;
                LDMATRIX_X4(bF[nb2 * 2][0], bF[nb2 * 2][1],
                            bF[nb2 * 2 + 1][0], bF[nb2 * 2 + 1][1], addr);
            }
            #pragma unroll
            for (int nb = 0; nb < 8; nb++)
                MMA16816(sc[nb][0], sc[nb][1], sc[nb][2], sc[nb][3],
                         aF[0], aF[1], aF[2], aF[3], bF[nb][0], bF[nb][1]);
        }

        float tm0 = -INFINITY, tm1 = -INFINITY;
        #pragma unroll
        for (int nb = 0; nb < 8; nb++) {
            float scol = (float)(s0 + nb * 8 + 2 * (lane & 3));
            sc[nb][0] = sc[nb][0] * SCALE_ - slope * fabsf(trow0 - scol);
            sc[nb][1] = sc[nb][1] * SCALE_ - slope * fabsf(trow0 - (scol + 1.f));
            sc[nb][2] = sc[nb][2] * SCALE_ - slope * fabsf(trow1 - scol);
            sc[nb][3] = sc[nb][3] * SCALE_ - slope * fabsf(trow1 - (scol + 1.f));
            tm0 = fmaxf(tm0, fmaxf(sc[nb][0], sc[nb][1]));
            tm1 = fmaxf(tm1, fmaxf(sc[nb][2], sc[nb][3]));
        }
        tm0 = fmaxf(tm0, __shfl_xor_sync(0xffffffffu, tm0, 1));
        tm0 = fmaxf(tm0, __shfl_xor_sync(0xffffffffu, tm0, 2));
        tm1 = fmaxf(tm1, __shfl_xor_sync(0xffffffffu, tm1, 1));
        tm1 = fmaxf(tm1, __shfl_xor_sync(0xffffffffu, tm1, 2));

        float mn0 = fmaxf(m0, tm0);
        float mn1 = fmaxf(m1, tm1);
        float cr0 = __expf(m0 - mn0);
        float cr1 = __expf(m1 - mn1);
        l0 *= cr0; l1 *= cr1;
        #pragma unroll
        for (int nb = 0; nb < 8; nb++) {
            oF[nb][0] *= cr0; oF[nb][1] *= cr0;
            oF[nb][2] *= cr1; oF[nb][3] *= cr1;
        }

        float rs0 = 0.f, rs1 = 0.f;
        #pragma unroll
        for (int nb = 0; nb < 8; nb++) {
            sc[nb][0] = __expf(sc[nb][0] - mn0);
            sc[nb][1] = __expf(sc[nb][1] - mn0);
            sc[nb][2] = __expf(sc[nb][2] - mn1);
            sc[nb][3] = __expf(sc[nb][3] - mn1);
            rs0 += sc[nb][0] + sc[nb][1];
            rs1 += sc[nb][2] + sc[nb][3];
        }
        rs0 += __shfl_xor_sync(0xffffffffu, rs0, 1);
        rs0 += __shfl_xor_sync(0xffffffffu, rs0, 2);
        rs1 += __shfl_xor_sync(0xffffffffu, rs1, 1);
        rs1 += __shfl_xor_sync(0xffffffffu, rs1, 2);
        l0 += rs0; l1 += rs1;
        m0 = mn0; m1 = mn1;

        uint32_t phi[4][4];
        #pragma unroll
        for (int ks = 0; ks < 4; ks++) {
            phi[ks][0] = pack_bf16x2(sc[2 * ks][0], sc[2 * ks][1]);
            phi[ks][1] = pack_bf16x2(sc[2 * ks][2], sc[2 * ks][3]);
            phi[ks][2] = pack_bf16x2(sc[2 * ks + 1][0], sc[2 * ks + 1][1]);
            phi[ks][3] = pack_bf16x2(sc[2 * ks + 1][2], sc[2 * ks + 1][3]);
        }

        #pragma unroll
        for (int ks = 0; ks < 12; ks++) {
            uint32_t bF[8][2];
            #pragma unroll
            for (int nb2 = 0; nb2 < 4; nb2++) {
                uint32_t addr = sV + (b_row + nb2 * 16) * APB + ks * 32 + b_koff;
                LDMATRIX_X4(bF[nb2 * 2][0], bF[nb2 * 2][1],
                            bF[nb2 * 2 + 1][0], bF[nb2 * 2 + 1][1], addr);
            }
            uint32_t aP[4];
            if (ks < 8) {
                const int kk = ks & 3;
                aP[0] = phi[kk][0]; aP[1] = phi[kk][1];
                aP[2] = phi[kk][2]; aP[3] = phi[kk][3];
            } else {
                const int kk = ks - 8;
                #pragma unroll
                for (int j = 0; j < 4; j++) {
                    const int nb = 2 * kk + (j >> 1);
                    const int ci = (j & 1) * 2;
                    float pe = sc[nb][ci]     - bf16lo_f(phi[kk][j]);
                    float po = sc[nb][ci + 1] - bf16hi_f(phi[kk][j]);
                    aP[j] = pack_bf16x2(pe, po);
                }
            }
            #pragma unroll
            for (int nb = 0; nb < 8; nb++)
                MMA16816(oF[nb][0], oF[nb][1], oF[nb][2], oF[nb][3],
                         aP[0], aP[1], aP[2], aP[3], bF[nb][0], bF[nb][1]);
        }
        __syncthreads();
    }

    const size_t base = (size_t)(split * B_ * H_ + hb) * T_;
    const size_t pidx0 = base + t0 + wid * 16 + r0;
    const size_t pidx1 = pidx0 + 8;
    #pragma unroll
    for (int nb = 0; nb < 8; nb++) {
        const int col = nb * 8 + 2 * (lane & 3);
        *(float2*)&g_pacc[pidx0 * HD_ + col] = make_float2(oF[nb][0], oF[nb][1]);
        *(float2*)&g_pacc[pidx1 * HD_ + col] = make_float2(oF[nb][2], oF[nb][3]);
    }
    if ((lane & 3) == 0) {
        g_pm[pidx0] = m0; g_pl[pidx0] = l0;
        g_pm[pidx1] = m1; g_pl[pidx1] = l1;
    }
}

// ---------------------------------------------------------------------------
// Combine split-KV partials -> split-act layout [b*T+t][hi|hi|lo] (g_as)
// ---------------------------------------------------------------------------
__global__ __launch_bounds__(256) void attn_combine_kernel(
    __nv_bfloat16* __restrict__ as_out)
{
    const int d = threadIdx.x & 63;
    const int rlocal = threadIdx.x >> 6;
    const size_t row = (size_t)blockIdx.x * 4 + rlocal;
    const int t = row % T_;
    const int h = (row / T_) % H_;
    const int b = row / ((size_t)T_ * H_);

    float m0 = g_pm[row];
    float l0 = g_pl[row];
    float m1 = g_pm[(size_t)B_ * H_ * T_ + row];
    float l1 = g_pl[(size_t)B_ * H_ * T_ + row];

    float M = fmaxf(m0, m1);
    float e0 = __expf(m0 - M), e1 = __expf(m1 - M);
    float L = l0 * e0 + l1 * e1;
    float inv = 1.f / L;

    float a0 = g_pacc[row * HD_ + d];
    float a1 = g_pacc[((size_t)B_ * H_ * T_ + row) * HD_ + d];
    float val = (a0 * e0 + a1 * e1) * inv;

    __nv_bfloat16 hi = __float2bfloat16(val);
    __nv_bfloat16 lo = __float2bfloat16(val - __bfloat162float(hi));
    const int c = h * 64 + d;
    __nv_bfloat16* orow = as_out + ((size_t)(b * T_ + t)) * KTOT;
    orow[c] = hi; orow[D_ + c] = hi; orow[2 * D_ + c] = lo;
}

// ---------------------------------------------------------------------------
// residual + RMSNorm
// ---------------------------------------------------------------------------
__global__ __launch_bounds__(256) void rms_kernel(
    const float* __restrict__ query, const float* __restrict__ proj,
    const float* __restrict__ w, float* __restrict__ out)
{
    __shared__ float sh[8];
    __shared__ float s_inv;
    const size_t row = blockIdx.x;
    const float* qr = query + row * D_;
    const float* pr = proj + row * D_;
    float* orow = out + row * D_;

    float x[4];
    float ss = 0.f;
    #pragma unroll
    for (int i = 0; i < 4; i++) {
        int idx = threadIdx.x + i * 256;
        x[i] = qr[idx] + pr[idx];
        ss += x[i] * x[i];
    }
    #pragma unroll
    for (int ofs = 16; ofs > 0; ofs >>= 1)
        ss += __shfl_xor_sync(0xffffffffu, ss, ofs);
    const int lane = threadIdx.x & 31, wid = threadIdx.x >> 5;
    if (lane == 0) sh[wid] = ss;
    __syncthreads();
    if (threadIdx.x == 0) {
        float tot = 0.f;
        #pragma unroll
        for (int i = 0; i < 8; i++) tot += sh[i];
        s_inv = rsqrtf(tot * (1.0f / D_) + RMS_EPS_);
    }
    __syncthreads();
    const float inv = s_inv;
    #pragma unroll
    for (int i = 0; i < 4; i++) {
        int idx = threadIdx.x + i * 256;
        orow[idx] = x[i] * inv * w[idx];
    }
}

// ---------------------------------------------------------------------------
extern "C" void kernel_launch(void* const* d_in, const int* in_sizes, int n_in,
                              void* d_out, int out_size)
{
    const float* query   = (const float*)d_in[0];
    const float* context = (const float*)d_in[1];
    const float* Wq      = (const float*)d_in[2];
    const float* Wk      = (const float*)d_in[3];
    const float* Wv      = (const float*)d_in[4];
    const float* Wo      = (const float*)d_in[5];
    const float* rmsw    = (const float*)d_in[6];
    float* out = (float*)d_out;

    float *pv, *pproj;
    cudaGetSymbolAddress((void**)&pv,    g_v);
    cudaGetSymbolAddress((void**)&pproj, g_proj);

    __nv_bfloat16 *qs, *cs, *as, *wqs, *wks, *wvs, *wos, *qe, *kke, *vte;
    cudaGetSymbolAddress((void**)&qs,  g_qs);
    cudaGetSymbolAddress((void**)&cs,  g_cs);
    cudaGetSymbolAddress((void**)&as,  g_as);
    cudaGetSymbolAddress((void**)&wqs, g_wqs);
    cudaGetSymbolAddress((void**)&wks, g_wks);
    cudaGetSymbolAddress((void**)&wvs, g_wvs);
    cudaGetSymbolAddress((void**)&wos, g_wos);
    cudaGetSymbolAddress((void**)&qe,  g_qe);
    cudaGetSymbolAddress((void**)&kke, g_ke);
    cudaGetSymbolAddress((void**)&vte, g_vte);

    const int SM2 = 4 * (128 * GPITCH + WSTAGE);   // 147456
    const int SM4 = 4 * (256 * GPITCH + WSTAGE);   // 221184
    cudaFuncSetAttribute(gemm_bf16_mma<2>,
        cudaFuncAttributeMaxDynamicSharedMemorySize, SM2);
    cudaFuncSetAttribute(gemm_bf16_mma<4>,
        cudaFuncAttributeMaxDynamicSharedMemorySize, SM4);
    cudaFuncSetAttribute(attn_mma,
        cudaFuncAttributeMaxDynamicSharedMemorySize, ATTN_SMEM);

    const int MQ = B_ * T_;   // 2048
    const int MK = B_ * S_;   // 4096

    // all input conversions in one launch
    split_all<<<10240, 256>>>(query, context, Wq, Wk, Wv, Wo);

    // projections
    dim3 gq(D_ / GTN, MQ / 128);    // MB=2
    dim3 gk(D_ / GTN, MK / 256);    // MB=4
    gemm_bf16_mma<2><<<gq, 256, SM2>>>(qs, wqs, nullptr, qe,  D_, 1, T_);
    gemm_bf16_mma<4><<<gk, 256, SM4>>>(cs, wks, nullptr, kke, D_, 2, S_);
    gemm_bf16_mma<4><<<gk, 256, SM4>>>(cs, wvs, pv, nullptr,  D_, 0, 0);

    v_ext_t<<<dim3(S_ / 32, 2, B_ * H_), dim3(32, 8)>>>(pv, vte);

    // tensor-core attention
    attn_mma<<<dim3(T_ / AM, NS_, B_ * H_), 256, ATTN_SMEM>>>(qe, kke, vte);
    attn_combine_kernel<<<(B_ * H_ * T_) / 4, 256>>>(as);

    // output projection
    gemm_bf16_mma<2><<<gq, 256, SM2>>>(as, wos, pproj, nullptr, D_, 0, 0);

    rms_kernel<<<MQ, 256>>>(query, pproj, rmsw, out);
}